// round 3
// baseline (speedup 1.0000x reference)
#include <cuda_runtime.h>

// Problem constants (fixed shapes from setup_inputs: n=2, C=4, d=96, h=160, w=160)
#define DHW   2457600          // 96*160*160
#define DHW4  614400           // DHW / 4
#define NB    2
#define NC    4
#define TOTAL_VOX 4915200.0    // NB * DHW
#define SMOOTH 1e-5

// Global accumulators (double to make atomic-ordering nondeterminism negligible):
// [0..3]  intersect[c]      sum of p[c] where target==c
// [4..7]  prob_sum[c]       sum of p[c] over all voxels
// [8..11] count[c]          #voxels with target==c
// [12]    pos_cnt  [13] neg_cnt  [14] bce_pos_sum  [15] bce_neg_sum
__device__ double g_acc[16];

__global__ void zero_acc_kernel() {
    if (threadIdx.x < 16) g_acc[threadIdx.x] = 0.0;
}

__global__ void __launch_bounds__(256)
reduce_kernel(const float* __restrict__ segin,
              const float* __restrict__ edgein,
              const int*   __restrict__ segmask,
              const int*   __restrict__ edgemask) {
    float inter0 = 0.f, inter1 = 0.f, inter2 = 0.f, inter3 = 0.f;
    float psum0  = 0.f, psum1  = 0.f, psum2  = 0.f, psum3  = 0.f;
    float cnt0   = 0.f, cnt1   = 0.f, cnt2   = 0.f, cnt3   = 0.f;
    float posc = 0.f, negc = 0.f, bcep = 0.f, bcen = 0.f;

    // batch handled by gridDim.y -> no integer division in the loop
    const int b = blockIdx.y;
    const float4* s  = (const float4*)(segin   + (size_t)b * NC * DHW);
    const float4* e  = (const float4*)(edgein  + (size_t)b * DHW);
    const int4*   tm = (const int4*)  (segmask + (size_t)b * DHW);
    const int4*   em = (const int4*)  (edgemask+ (size_t)b * DHW);

    const int stride = gridDim.x * blockDim.x;

    for (int v = blockIdx.x * blockDim.x + threadIdx.x; v < DHW4; v += stride) {
        float4 x0 = __ldg(&s[v]);
        float4 x1 = __ldg(&s[v +     DHW4]);
        float4 x2 = __ldg(&s[v + 2 * DHW4]);
        float4 x3 = __ldg(&s[v + 3 * DHW4]);
        int4   t  = __ldg(&tm[v]);
        float4 ev = __ldg(&e[v]);
        int4   et = __ldg(&em[v]);

        const float a0[4] = {x0.x, x0.y, x0.z, x0.w};
        const float a1[4] = {x1.x, x1.y, x1.z, x1.w};
        const float a2[4] = {x2.x, x2.y, x2.z, x2.w};
        const float a3[4] = {x3.x, x3.y, x3.z, x3.w};
        const int   tt[4] = {t.x, t.y, t.z, t.w};
        const float ee[4] = {ev.x, ev.y, ev.z, ev.w};
        const int   eb[4] = {et.x, et.y, et.z, et.w};

        #pragma unroll
        for (int j = 0; j < 4; j++) {
            // --- softmax over 4 channels ---
            float ca = a0[j], cb = a1[j], cc = a2[j], cd = a3[j];
            float m  = fmaxf(fmaxf(ca, cb), fmaxf(cc, cd));
            float p0 = __expf(ca - m);
            float p1 = __expf(cb - m);
            float p2 = __expf(cc - m);
            float p3 = __expf(cd - m);
            float inv = __frcp_rn(p0 + p1 + p2 + p3);
            p0 *= inv; p1 *= inv; p2 *= inv; p3 *= inv;

            psum0 += p0; psum1 += p1; psum2 += p2; psum3 += p3;

            const int c = tt[j];
            // predicated (no dynamic local-array indexing -> stays in registers)
            if (c == 0) { inter0 += p0; cnt0 += 1.f; }
            if (c == 1) { inter1 += p1; cnt1 += 1.f; }
            if (c == 2) { inter2 += p2; cnt2 += 1.f; }
            if (c == 3) { inter3 += p3; cnt3 += 1.f; }

            // --- stable BCE-with-logits ---
            const float x = ee[j];
            const int   y = eb[j];
            float bce = fmaxf(x, 0.f) - x * (float)(y == 1)
                      + log1pf(__expf(-fabsf(x)));
            if (y == 1)      { posc += 1.f; bcep += bce; }
            else if (y == 0) { negc += 1.f; bcen += bce; }
        }
    }

    // ---- block reduction of 16 accumulators ----
    float acc[16] = {inter0, inter1, inter2, inter3,
                     psum0,  psum1,  psum2,  psum3,
                     cnt0,   cnt1,   cnt2,   cnt3,
                     posc,   negc,   bcep,   bcen};

    #pragma unroll
    for (int k = 0; k < 16; k++) {
        #pragma unroll
        for (int o = 16; o > 0; o >>= 1)
            acc[k] += __shfl_down_sync(0xFFFFFFFFu, acc[k], o);
    }

    __shared__ float sh[8][16];
    const int warp = threadIdx.x >> 5;
    const int lane = threadIdx.x & 31;
    if (lane == 0) {
        #pragma unroll
        for (int k = 0; k < 16; k++) sh[warp][k] = acc[k];
    }
    __syncthreads();

    if (threadIdx.x < 16) {
        float v = 0.f;
        #pragma unroll
        for (int w = 0; w < 8; w++) v += sh[w][threadIdx.x];
        atomicAdd(&g_acc[threadIdx.x], (double)v);
    }
}

__global__ void finalize_kernel(float* out) {
    // soft dice
    double dice_sum = 0.0;
    #pragma unroll
    for (int c = 0; c < NC; c++) {
        double inter = g_acc[c];
        double denom = g_acc[4 + c] + g_acc[8 + c];
        dice_sum += (2.0 * inter + SMOOTH) / (denom + SMOOTH);
    }
    out[0] = (float)(1.0 - dice_sum / (double)NC);

    // weighted BCE:  mean(weight*bce) = (neg*S_pos + pos*S_neg) / (sum * total)
    double pos = g_acc[12], neg = g_acc[13];
    double sum = pos + neg;
    out[1] = (float)((neg * g_acc[14] + pos * g_acc[15]) / (sum * TOTAL_VOX));
}

extern "C" void kernel_launch(void* const* d_in, const int* in_sizes, int n_in,
                              void* d_out, int out_size) {
    const float* segin    = (const float*)d_in[0];
    const float* edgein   = (const float*)d_in[1];
    const int*   segmask  = (const int*)d_in[2];
    const int*   edgemask = (const int*)d_in[3];
    float* out = (float*)d_out;

    zero_acc_kernel<<<1, 32>>>();
    dim3 grid(592, NB);
    reduce_kernel<<<grid, 256>>>(segin, edgein, segmask, edgemask);
    finalize_kernel<<<1, 1>>>(out);
}